// round 10
// baseline (speedup 1.0000x reference)
#include <cuda_runtime.h>
#include <cuda_fp16.h>
#include <cstdint>

#define NN 50000
#define EE 600000
#define ET (EE + NN)
#define SCAN_B 1024
#define NBLK ((NN + SCAN_B - 1) / SCAN_B)
#define NHALF 25088              // 196 * 128
#define NREST (NN - NHALF)       // 24912

// ---------------- scratch ---------------------------------------------------------
__device__ __half g_ahi[(size_t)NN * 256];      // layer input (fp16)
__device__ __half g_h0[(size_t)NN * 256];       // h buffer, layers 0 & 2
__device__ __half g_h1[(size_t)NN * 256];       // h buffer, layer 1
__device__ __half g_w0hi[256 * 256], g_w0lo[256 * 256];
__device__ __half g_w1hi[256 * 256], g_w1lo[256 * 256];
__device__ __half g_w2hi[64 * 256],  g_w2lo[64 * 256];
__device__ float g_as0[NN * 4], g_ad0[NN * 4];  // alphas, layers 0 & 2
__device__ float g_as1[NN * 4], g_ad1[NN * 4];  // alphas, layer 1
__device__ int   g_cnt[NN];
__device__ int   g_incl[NBLK * SCAN_B];
__device__ int   g_bsum[NBLK];
__device__ int   g_rowptr[NN + 1];
__device__ int   g_fill[NN];
__device__ int   g_col[ET];

// ---------------- PTX helpers -----------------------------------------------------
__device__ __forceinline__ uint32_t smem_u32(const void* p) {
    uint32_t a;
    asm("{ .reg .u64 t; cvta.to.shared.u64 t, %1; cvt.u32.u64 %0, t; }" : "=r"(a) : "l"(p));
    return a;
}
__device__ __forceinline__ void cp_async16(uint32_t dst, const void* src) {
    asm volatile("cp.async.cg.shared.global [%0], [%1], 16;"
                 :: "r"(dst), "l"(__cvta_generic_to_global(src)) : "memory");
}
__device__ __forceinline__ void ldsm_x4(uint32_t& r0, uint32_t& r1, uint32_t& r2,
                                        uint32_t& r3, uint32_t addr) {
    asm volatile("ldmatrix.sync.aligned.m8n8.x4.shared.b16 {%0,%1,%2,%3}, [%4];"
                 : "=r"(r0), "=r"(r1), "=r"(r2), "=r"(r3) : "r"(addr));
}
__device__ __forceinline__ void mma16816(float* c, const uint32_t* a, const uint32_t* b) {
    asm volatile("mma.sync.aligned.m16n8k16.row.col.f32.f16.f16.f32 "
                 "{%0,%1,%2,%3}, {%4,%5,%6,%7}, {%8,%9}, {%0,%1,%2,%3};"
                 : "+f"(c[0]), "+f"(c[1]), "+f"(c[2]), "+f"(c[3])
                 : "r"(a[0]), "r"(a[1]), "r"(a[2]), "r"(a[3]), "r"(b[0]), "r"(b[1]));
}
#define SW128(o) ((o) ^ (((o) >> 3) & 0x70))

__device__ __forceinline__ void split2(float v, __half& hi, __half& lo) {
    hi = __float2half_rn(v);
    lo = __float2half_rn(v - __half2float(hi));
}

// ---------------- conversions -----------------------------------------------------
__global__ void k_tofp16_x(const float* __restrict__ x) {
    int i = blockIdx.x * blockDim.x + threadIdx.x;
    if (i >= NN * 64) return;
    float4 v = ((const float4*)x)[i];
    ((__half2*)g_ahi)[2 * i]     = __floats2half2_rn(v.x, v.y);
    ((__half2*)g_ahi)[2 * i + 1] = __floats2half2_rn(v.z, v.w);
}

template <int NO>
__global__ void k_split_wt(const float* __restrict__ W, __half* __restrict__ hi,
                           __half* __restrict__ lo) {
    int i = blockIdx.x * blockDim.x + threadIdx.x;
    if (i >= 256 * NO) return;
    int k = i / NO, n = i % NO;
    __half h, l;
    split2(W[i], h, l);
    hi[n * 256 + k] = h;
    lo[n * 256 + k] = l;
}

// ---------------- GEMM: 8 warps, A fp16, B hi/lo (2 passes), fused alpha ----------
template <int NO>
__global__ __launch_bounds__(256, 2) void k_gemm_mma(const __half* __restrict__ A,
                                                     const __half* __restrict__ Bhi,
                                                     const __half* __restrict__ Blo,
                                                     __half* __restrict__ Hhi,
                                                     const float* __restrict__ a_s,
                                                     const float* __restrict__ a_d,
                                                     float* __restrict__ as_out,
                                                     float* __restrict__ ad_out,
                                                     int m0) {
    constexpr int BM = 128, BN = (NO == 256) ? 128 : 64;
    constexpr int WN = BN / 2;
    constexpr int NG = WN / 8;
    constexpr int ASZ = 128 * 128;
    constexpr int BSZ = BN * 128;
    constexpr int STG = ASZ + 2 * BSZ;

    extern __shared__ __align__(1024) char smraw[];
    const uint32_t sb = smem_u32(smraw);
    const int tid = threadIdx.x, w = tid >> 5, lane = tid & 31;
    const int wm = w & 3, wn = w >> 2;
    const int bm = m0 + blockIdx.y * BM, bn = blockIdx.x * BN;

    auto load = [&](int c) {
        const uint32_t st = sb + (c & 1) * STG;
        const int ko = c * 64;
        for (int t = tid; t < 128 * 8; t += 256) {
            int r = t >> 3, q = t & 7;
            int gr = bm + r; if (gr >= NN) gr = NN - 1;
            cp_async16(st + SW128(r * 128 + q * 16), A + (size_t)gr * 256 + ko + q * 8);
        }
        for (int t = tid; t < BN * 8; t += 256) {
            int r = t >> 3, q = t & 7;
            size_t go = (size_t)(bn + r) * 256 + ko + q * 8;
            uint32_t so = SW128(r * 128 + q * 16);
            cp_async16(st + ASZ + so, Bhi + go);
            cp_async16(st + ASZ + BSZ + so, Blo + go);
        }
        asm volatile("cp.async.commit_group;" ::: "memory");
    };

    load(0);
    load(1);

    float acc[2][NG][4] = {};
    const int a_row = wm * 32 + (lane & 15);
    const int a_colq = (lane >> 4) * 16;
    const int b_row = wn * WN + (lane >> 4) * 8 + (lane & 7);
    const int b_colq = ((lane >> 3) & 1) * 16;

    for (int c = 0; c < 4; ++c) {
        const uint32_t st = sb + (c & 1) * STG;
        if (c < 3) asm volatile("cp.async.wait_group 1;" ::: "memory");
        else       asm volatile("cp.async.wait_group 0;" ::: "memory");
        __syncthreads();
#pragma unroll
        for (int kk = 0; kk < 4; ++kk) {
            uint32_t ah[8], bb[2 * NG];
#pragma unroll
            for (int f = 0; f < 2; ++f)
                ldsm_x4(ah[f * 4], ah[f * 4 + 1], ah[f * 4 + 2], ah[f * 4 + 3],
                        st + SW128((a_row + f * 16) * 128 + kk * 32 + a_colq));
#pragma unroll
            for (int g2 = 0; g2 < NG / 2; ++g2)
                ldsm_x4(bb[g2 * 4], bb[g2 * 4 + 1], bb[g2 * 4 + 2], bb[g2 * 4 + 3],
                        st + ASZ + SW128((b_row + g2 * 16) * 128 + kk * 32 + b_colq));
#pragma unroll
            for (int f = 0; f < 2; ++f)
#pragma unroll
                for (int g = 0; g < NG; ++g)
                    mma16816(acc[f][g], ah + f * 4, bb + g * 2);
#pragma unroll
            for (int g2 = 0; g2 < NG / 2; ++g2)
                ldsm_x4(bb[g2 * 4], bb[g2 * 4 + 1], bb[g2 * 4 + 2], bb[g2 * 4 + 3],
                        st + ASZ + BSZ + SW128((b_row + g2 * 16) * 128 + kk * 32 + b_colq));
#pragma unroll
            for (int f = 0; f < 2; ++f)
#pragma unroll
                for (int g = 0; g < NG; ++g)
                    mma16816(acc[f][g], ah + f * 4, bb + g * 2);
        }
        __syncthreads();
        if (c + 2 < 4) load(c + 2);
    }

    if constexpr (NO == 256) {
        const int head = blockIdx.x * 2 + wn;
        float as_r[2 * NG], ad_r[2 * NG];
#pragma unroll
        for (int g = 0; g < NG; ++g) {
            int cl = head * 64 + g * 8 + (lane & 3) * 2;
            as_r[g * 2] = a_s[cl];     as_r[g * 2 + 1] = a_s[cl + 1];
            ad_r[g * 2] = a_d[cl];     ad_r[g * 2 + 1] = a_d[cl + 1];
        }
#pragma unroll
        for (int f = 0; f < 2; ++f) {
#pragma unroll
            for (int rr = 0; rr < 2; ++rr) {
                float ps = 0.f, pd = 0.f;
#pragma unroll
                for (int g = 0; g < NG; ++g) {
                    float c0 = acc[f][g][rr * 2], c1 = acc[f][g][rr * 2 + 1];
                    ps += c0 * as_r[g * 2] + c1 * as_r[g * 2 + 1];
                    pd += c0 * ad_r[g * 2] + c1 * ad_r[g * 2 + 1];
                }
                ps += __shfl_xor_sync(0xffffffffu, ps, 1);
                ps += __shfl_xor_sync(0xffffffffu, ps, 2);
                pd += __shfl_xor_sync(0xffffffffu, pd, 1);
                pd += __shfl_xor_sync(0xffffffffu, pd, 2);
                int m = bm + wm * 32 + f * 16 + rr * 8 + (lane >> 2);
                if ((lane & 3) == 0 && m < NN) {
                    as_out[m * 4 + head] = ps;
                    ad_out[m * 4 + head] = pd;
                }
            }
        }
#pragma unroll
        for (int f = 0; f < 2; ++f) {
#pragma unroll
            for (int g = 0; g < NG; ++g) {
                int m = bm + wm * 32 + f * 16 + (lane >> 2);
                int n = bn + wn * 64 + g * 8 + (lane & 3) * 2;
#pragma unroll
                for (int rr = 0; rr < 2; ++rr) {
                    int mm = m + rr * 8;
                    if (mm < NN)
                        *(__half2*)(Hhi + (size_t)mm * NO + n) =
                            __floats2half2_rn(acc[f][g][rr * 2], acc[f][g][rr * 2 + 1]);
                }
            }
        }
    } else {
        // store Hhi
#pragma unroll
        for (int f = 0; f < 2; ++f) {
#pragma unroll
            for (int g = 0; g < NG; ++g) {
                int m = bm + wm * 32 + f * 16 + (lane >> 2);
                int n = bn + wn * WN + g * 8 + (lane & 3) * 2;
#pragma unroll
                for (int rr = 0; rr < 2; ++rr) {
                    int mm = m + rr * 8;
                    if (mm < NN)
                        *(__half2*)(Hhi + (size_t)mm * NO + n) =
                            __floats2half2_rn(acc[f][g][rr * 2], acc[f][g][rr * 2 + 1]);
                }
            }
        }
        // fused alpha (H=1): cross-warp (wn 0/1) reduction via reused tile smem
        float as_r[2 * NG], ad_r[2 * NG];
#pragma unroll
        for (int g = 0; g < NG; ++g) {
            int cl = wn * 32 + g * 8 + (lane & 3) * 2;
            as_r[g * 2] = a_s[cl];     as_r[g * 2 + 1] = a_s[cl + 1];
            ad_r[g * 2] = a_d[cl];     ad_r[g * 2 + 1] = a_d[cl + 1];
        }
        float psv[2][2], pdv[2][2];
#pragma unroll
        for (int f = 0; f < 2; ++f) {
#pragma unroll
            for (int rr = 0; rr < 2; ++rr) {
                float ps = 0.f, pd = 0.f;
#pragma unroll
                for (int g = 0; g < NG; ++g) {
                    float c0 = acc[f][g][rr * 2], c1 = acc[f][g][rr * 2 + 1];
                    ps += c0 * as_r[g * 2] + c1 * as_r[g * 2 + 1];
                    pd += c0 * ad_r[g * 2] + c1 * ad_r[g * 2 + 1];
                }
                ps += __shfl_xor_sync(0xffffffffu, ps, 1);
                ps += __shfl_xor_sync(0xffffffffu, ps, 2);
                pd += __shfl_xor_sync(0xffffffffu, pd, 1);
                pd += __shfl_xor_sync(0xffffffffu, pd, 2);
                psv[f][rr] = ps; pdv[f][rr] = pd;
            }
        }
        float* red = (float*)smraw;  // tiles dead after final sync; 256 floats
        if (wn == 0 && (lane & 3) == 0) {
#pragma unroll
            for (int f = 0; f < 2; ++f)
#pragma unroll
                for (int rr = 0; rr < 2; ++rr) {
                    int row = wm * 32 + f * 16 + rr * 8 + (lane >> 2);
                    red[row] = psv[f][rr];
                    red[128 + row] = pdv[f][rr];
                }
        }
        __syncthreads();
        if (wn == 1 && (lane & 3) == 0) {
#pragma unroll
            for (int f = 0; f < 2; ++f)
#pragma unroll
                for (int rr = 0; rr < 2; ++rr) {
                    int row = wm * 32 + f * 16 + rr * 8 + (lane >> 2);
                    int m = bm + row;
                    if (m < NN) {
                        as_out[m] = red[row] + psv[f][rr];
                        ad_out[m] = red[128 + row] + pdv[f][rr];
                    }
                }
        }
    }
}

// ---------------- CSR build -------------------------------------------------------
__global__ void k_zero_cnt() {
    int i = blockIdx.x * blockDim.x + threadIdx.x;
    if (i < NN) g_cnt[i] = 0;
}
__global__ void k_count(const int* __restrict__ ei) {
    int e = blockIdx.x * blockDim.x + threadIdx.x;
    if (e >= ET) return;
    int d = (e < EE) ? ei[EE + e] : (e - EE);
    atomicAdd(&g_cnt[d], 1);
}
__global__ void k_scan1() {
    __shared__ int sh[SCAN_B];
    int tid = threadIdx.x;
    int i = blockIdx.x * SCAN_B + tid;
    int v = (i < NN) ? g_cnt[i] : 0;
    sh[tid] = v;
    __syncthreads();
    for (int off = 1; off < SCAN_B; off <<= 1) {
        int t = (tid >= off) ? sh[tid - off] : 0;
        __syncthreads();
        sh[tid] += t;
        __syncthreads();
    }
    g_incl[i] = sh[tid];
    if (tid == SCAN_B - 1) g_bsum[blockIdx.x] = sh[tid];
}
__global__ void k_scan2() {
    if (threadIdx.x == 0) {
        int s = 0;
        for (int i = 0; i < NBLK; ++i) { int t = g_bsum[i]; g_bsum[i] = s; s += t; }
    }
}
__global__ void k_scan3() {
    int i = blockIdx.x * blockDim.x + threadIdx.x;
    if (i < NN) {
        int v = g_cnt[i];
        int ex = g_incl[i] - v + g_bsum[i >> 10];
        g_rowptr[i] = ex;
        g_fill[i] = ex;
    }
    if (i == 0) g_rowptr[NN] = ET;
}
__global__ void k_fill(const int* __restrict__ ei) {
    int e = blockIdx.x * blockDim.x + threadIdx.x;
    if (e >= ET) return;
    int s, d;
    if (e < EE) { s = ei[e]; d = ei[EE + e]; }
    else        { s = e - EE; d = s; }
    int pos = atomicAdd(&g_fill[d], 1);
    g_col[pos] = s;
}

// ---------------- GAT conv: online softmax + fp16 message gather ------------------
template <int HEADS, bool RELU, bool SPLIT>
__global__ __launch_bounds__(256) void k_conv(const __half* __restrict__ h,
                                              const float* __restrict__ as_,
                                              const float* __restrict__ ad_,
                                              const float* __restrict__ bias,
                                              float* __restrict__ out,
                                              __half* __restrict__ ohi,
                                              int base, int nnodes) {
    const int TC = HEADS * 64;
    const int NPL = TC / 32;
    int local = (blockIdx.x * blockDim.x + threadIdx.x) >> 5;
    int lane = threadIdx.x & 31;
    if (local >= nnodes) return;
    int warp = base + local;
    int beg = g_rowptr[warp], end = g_rowptr[warp + 1];

    float adh[HEADS];
#pragma unroll
    for (int hh = 0; hh < HEADS; ++hh) adh[hh] = ad_[warp * HEADS + hh];

    float mx[HEADS], sm[HEADS];
#pragma unroll
    for (int hh = 0; hh < HEADS; ++hh) { mx[hh] = -1e30f; sm[hh] = 0.f; }
    for (int i = beg + lane; i < end; i += 32) {
        int s = g_col[i];
        float ev[HEADS];
        if constexpr (HEADS == 4) {
            float4 a4 = ((const float4*)as_)[s];
            ev[0] = a4.x; ev[1] = a4.y; ev[2] = a4.z; ev[3] = a4.w;
        } else {
            ev[0] = as_[s];
        }
#pragma unroll
        for (int hh = 0; hh < HEADS; ++hh) {
            float e = ev[hh] + adh[hh];
            e = e > 0.f ? e : 0.2f * e;
            if (e > mx[hh]) {
                sm[hh] = sm[hh] * __expf(mx[hh] - e) + 1.f;
                mx[hh] = e;
            } else {
                sm[hh] += __expf(e - mx[hh]);
            }
        }
    }
#pragma unroll
    for (int hh = 0; hh < HEADS; ++hh) {
#pragma unroll
        for (int o = 16; o; o >>= 1) {
            float mo = __shfl_xor_sync(0xffffffffu, mx[hh], o);
            float so = __shfl_xor_sync(0xffffffffu, sm[hh], o);
            float mn = fmaxf(mx[hh], mo);
            sm[hh] = sm[hh] * __expf(mx[hh] - mn) + so * __expf(mo - mn);
            mx[hh] = mn;
        }
    }

    const int myhead = (lane * NPL) / 64;
    float mm = mx[myhead], adm = adh[myhead], inv = 1.f / sm[myhead];
    float acc[NPL] = {};
#pragma unroll 4
    for (int i = beg; i < end; ++i) {
        int s = g_col[i];
        float e = as_[s * HEADS + myhead] + adm;
        e = e > 0.f ? e : 0.2f * e;
        float w = __expf(e - mm) * inv;
        const __half* hp = h + (size_t)s * TC + lane * NPL;
        if constexpr (NPL == 8) {
            uint4 raw = *(const uint4*)hp;
            float2 f0 = __half22float2(*(__half2*)&raw.x);
            float2 f1 = __half22float2(*(__half2*)&raw.y);
            float2 f2 = __half22float2(*(__half2*)&raw.z);
            float2 f3 = __half22float2(*(__half2*)&raw.w);
            acc[0] += w * f0.x; acc[1] += w * f0.y; acc[2] += w * f1.x; acc[3] += w * f1.y;
            acc[4] += w * f2.x; acc[5] += w * f2.y; acc[6] += w * f3.x; acc[7] += w * f3.y;
        } else {
            uint32_t raw = *(const uint32_t*)hp;
            float2 f0 = __half22float2(*(__half2*)&raw);
            acc[0] += w * f0.x; acc[1] += w * f0.y;
        }
    }
    float dinv = 1.f / (float)(end - beg);
    float v[NPL];
#pragma unroll
    for (int j = 0; j < NPL; ++j) {
        v[j] = acc[j] * dinv + bias[lane * NPL + j];
        if (RELU) v[j] = fmaxf(v[j], 0.f);
    }
    if constexpr (SPLIT) {
        __half2 vh[NPL / 2];
#pragma unroll
        for (int j = 0; j < NPL / 2; ++j)
            vh[j] = __floats2half2_rn(v[2 * j], v[2 * j + 1]);
        *(uint4*)(ohi + (size_t)warp * TC + lane * NPL) = *(uint4*)vh;
    } else {
#pragma unroll
        for (int j = 0; j < NPL; ++j)
            out[(size_t)warp * TC + lane * NPL + j] = v[j];
    }
}

// ---------------- launch ----------------------------------------------------------
extern "C" void kernel_launch(void* const* d_in, const int* in_sizes, int n_in,
                              void* d_out, int out_size) {
    const float* x   = (const float*)d_in[0];
    const int*   ei  = (const int*)d_in[1];
    const float* W0  = (const float*)d_in[2];
    const float* a0s = (const float*)d_in[3];
    const float* a0d = (const float*)d_in[4];
    const float* b0  = (const float*)d_in[5];
    const float* W1  = (const float*)d_in[6];
    const float* a1s = (const float*)d_in[7];
    const float* a1d = (const float*)d_in[8];
    const float* b1  = (const float*)d_in[9];
    const float* W2  = (const float*)d_in[10];
    const float* a2s = (const float*)d_in[11];
    const float* a2d = (const float*)d_in[12];
    const float* b2  = (const float*)d_in[13];
    float* out = (float*)d_out;

    void* p;
    cudaGetSymbolAddress(&p, g_ahi);  __half* ahi = (__half*)p;
    cudaGetSymbolAddress(&p, g_h0);   __half* h0 = (__half*)p;
    cudaGetSymbolAddress(&p, g_h1);   __half* h1 = (__half*)p;
    cudaGetSymbolAddress(&p, g_w0hi); __half* w0hi = (__half*)p;
    cudaGetSymbolAddress(&p, g_w0lo); __half* w0lo = (__half*)p;
    cudaGetSymbolAddress(&p, g_w1hi); __half* w1hi = (__half*)p;
    cudaGetSymbolAddress(&p, g_w1lo); __half* w1lo = (__half*)p;
    cudaGetSymbolAddress(&p, g_w2hi); __half* w2hi = (__half*)p;
    cudaGetSymbolAddress(&p, g_w2lo); __half* w2lo = (__half*)p;
    cudaGetSymbolAddress(&p, g_as0);  float* as0 = (float*)p;
    cudaGetSymbolAddress(&p, g_ad0);  float* ad0 = (float*)p;
    cudaGetSymbolAddress(&p, g_as1);  float* as1 = (float*)p;
    cudaGetSymbolAddress(&p, g_ad1);  float* ad1 = (float*)p;

    const int SMEM256 = 2 * (128 * 128 + 2 * 128 * 128);  // 98304
    const int SMEM64  = 2 * (128 * 128 + 2 * 64 * 128);   // 65536

    static cudaStream_t s2 = nullptr;
    static cudaEvent_t ev_fork, ev_w0, ev_csr, ev_wts, ev_a0, ev_g1a, ev_a1, ev_g2a;
    if (!s2) {
        cudaFuncSetAttribute(k_gemm_mma<256>, cudaFuncAttributeMaxDynamicSharedMemorySize, SMEM256);
        cudaFuncSetAttribute(k_gemm_mma<64>,  cudaFuncAttributeMaxDynamicSharedMemorySize, SMEM64);
        cudaStreamCreateWithFlags(&s2, cudaStreamNonBlocking);
        cudaEventCreateWithFlags(&ev_fork, cudaEventDisableTiming);
        cudaEventCreateWithFlags(&ev_w0,   cudaEventDisableTiming);
        cudaEventCreateWithFlags(&ev_csr,  cudaEventDisableTiming);
        cudaEventCreateWithFlags(&ev_wts,  cudaEventDisableTiming);
        cudaEventCreateWithFlags(&ev_a0,   cudaEventDisableTiming);
        cudaEventCreateWithFlags(&ev_g1a,  cudaEventDisableTiming);
        cudaEventCreateWithFlags(&ev_a1,   cudaEventDisableTiming);
        cudaEventCreateWithFlags(&ev_g2a,  cudaEventDisableTiming);
    }

    const int BLK_A = NHALF / 8;                 // 3136
    const int BLK_B = NREST / 8;                 // 3114
    const int BLK_ALL = (NN + 7) / 8;            // 6250
    dim3 gA256(2, NHALF / 128), gB256(2, (NREST + 127) / 128);
    dim3 gA64(1, NHALF / 128),  gB64(1, (NREST + 127) / 128);
    dim3 gF256(2, (NN + 127) / 128);

    // ---- fork: side stream does W0 split, CSR, W1/W2 splits ----
    cudaEventRecord(ev_fork, 0);
    cudaStreamWaitEvent(s2, ev_fork, 0);
    k_split_wt<256><<<(256 * 256 + 255) / 256, 256, 0, s2>>>(W0, w0hi, w0lo);
    cudaEventRecord(ev_w0, s2);
    k_zero_cnt<<<(NN + 255) / 256, 256, 0, s2>>>();
    k_count<<<(ET + 255) / 256, 256, 0, s2>>>(ei);
    k_scan1<<<NBLK, SCAN_B, 0, s2>>>();
    k_scan2<<<1, 32, 0, s2>>>();
    k_scan3<<<(NN + 255) / 256, 256, 0, s2>>>();
    k_fill<<<(ET + 255) / 256, 256, 0, s2>>>(ei);
    cudaEventRecord(ev_csr, s2);
    k_split_wt<256><<<(256 * 256 + 255) / 256, 256, 0, s2>>>(W1, w1hi, w1lo);
    k_split_wt<64><<<(256 * 64 + 255) / 256, 256, 0, s2>>>(W2, w2hi, w2lo);
    cudaEventRecord(ev_wts, s2);

    // ---- main: layer 0 ----
    k_tofp16_x<<<(NN * 64 + 255) / 256, 256>>>(x);
    cudaStreamWaitEvent(0, ev_w0, 0);
    k_gemm_mma<256><<<gF256, 256, SMEM256>>>(ahi, w0hi, w0lo, h0, a0s, a0d, as0, ad0, 0);
    cudaStreamWaitEvent(0, ev_csr, 0);
    k_conv<4, true, true><<<BLK_A, 256>>>(h0, as0, ad0, b0, nullptr, ahi, 0, NHALF);
    cudaEventRecord(ev_a0, 0);
    k_conv<4, true, true><<<BLK_B, 256>>>(h0, as0, ad0, b0, nullptr, ahi, NHALF, NREST);

    // ---- layer 1: gemm1_A overlaps conv0_B ----
    cudaStreamWaitEvent(s2, ev_a0, 0);
    k_gemm_mma<256><<<gA256, 256, SMEM256, s2>>>(ahi, w1hi, w1lo, h1, a1s, a1d, as1, ad1, 0);
    cudaEventRecord(ev_g1a, s2);
    cudaStreamWaitEvent(0, ev_wts, 0);
    k_gemm_mma<256><<<gB256, 256, SMEM256>>>(ahi, w1hi, w1lo, h1, a1s, a1d, as1, ad1, NHALF);
    cudaStreamWaitEvent(0, ev_g1a, 0);
    k_conv<4, true, true><<<BLK_A, 256>>>(h1, as1, ad1, b1, nullptr, ahi, 0, NHALF);
    cudaEventRecord(ev_a1, 0);
    k_conv<4, true, true><<<BLK_B, 256>>>(h1, as1, ad1, b1, nullptr, ahi, NHALF, NREST);

    // ---- layer 2: gemm2_A overlaps conv1_B; alpha fused in gemm epilogue ----
    cudaStreamWaitEvent(s2, ev_a1, 0);
    k_gemm_mma<64><<<gA64, 256, SMEM64, s2>>>(ahi, w2hi, w2lo, h0, a2s, a2d, as0, ad0, 0);
    cudaEventRecord(ev_g2a, s2);
    k_gemm_mma<64><<<gB64, 256, SMEM64>>>(ahi, w2hi, w2lo, h0, a2s, a2d, as0, ad0, NHALF);
    cudaStreamWaitEvent(0, ev_g2a, 0);
    k_conv<1, false, false><<<BLK_ALL, 256>>>(h0, as0, ad0, b2, out, nullptr, 0, NN);
}

// round 11
// speedup vs baseline: 1.0180x; 1.0180x over previous
#include <cuda_runtime.h>
#include <cuda_fp16.h>
#include <cstdint>

#define NN 50000
#define EE 600000
#define ET (EE + NN)
#define SCAN_B 1024
#define NBLK ((NN + SCAN_B - 1) / SCAN_B)

// ---------------- scratch ---------------------------------------------------------
__device__ __half g_ahi[(size_t)NN * 256];      // layer input (fp16)
__device__ __half g_hhi[(size_t)NN * 256];      // GEMM output hi
__device__ __half g_w0hi[256 * 256], g_w0lo[256 * 256];
__device__ __half g_w1hi[256 * 256], g_w1lo[256 * 256];
__device__ __half g_w2hi[64 * 256],  g_w2lo[64 * 256];
__device__ float g_as[NN * 4];
__device__ float g_ad[NN * 4];
__device__ int   g_cnt[NN];
__device__ int   g_incl[NBLK * SCAN_B];
__device__ int   g_bsum[NBLK];
__device__ int   g_rowptr[NN + 1];
__device__ int   g_fill[NN];
__device__ int   g_col[ET];

// ---------------- PTX helpers -----------------------------------------------------
__device__ __forceinline__ uint32_t smem_u32(const void* p) {
    uint32_t a;
    asm("{ .reg .u64 t; cvta.to.shared.u64 t, %1; cvt.u32.u64 %0, t; }" : "=r"(a) : "l"(p));
    return a;
}
__device__ __forceinline__ void cp_async16(uint32_t dst, const void* src) {
    asm volatile("cp.async.cg.shared.global [%0], [%1], 16;"
                 :: "r"(dst), "l"(__cvta_generic_to_global(src)) : "memory");
}
__device__ __forceinline__ void ldsm_x4(uint32_t& r0, uint32_t& r1, uint32_t& r2,
                                        uint32_t& r3, uint32_t addr) {
    asm volatile("ldmatrix.sync.aligned.m8n8.x4.shared.b16 {%0,%1,%2,%3}, [%4];"
                 : "=r"(r0), "=r"(r1), "=r"(r2), "=r"(r3) : "r"(addr));
}
__device__ __forceinline__ void mma16816(float* c, const uint32_t* a, const uint32_t* b) {
    asm volatile("mma.sync.aligned.m16n8k16.row.col.f32.f16.f16.f32 "
                 "{%0,%1,%2,%3}, {%4,%5,%6,%7}, {%8,%9}, {%0,%1,%2,%3};"
                 : "+f"(c[0]), "+f"(c[1]), "+f"(c[2]), "+f"(c[3])
                 : "r"(a[0]), "r"(a[1]), "r"(a[2]), "r"(a[3]), "r"(b[0]), "r"(b[1]));
}
#define SW128(o) ((o) ^ (((o) >> 3) & 0x70))

__device__ __forceinline__ void split2(float v, __half& hi, __half& lo) {
    hi = __float2half_rn(v);
    lo = __float2half_rn(v - __half2float(hi));
}

// ---------------- conversions -----------------------------------------------------
__global__ void k_tofp16_x(const float* __restrict__ x) {
    int i = blockIdx.x * blockDim.x + threadIdx.x;
    if (i >= NN * 64) return;
    float4 v = ((const float4*)x)[i];
    ((__half2*)g_ahi)[2 * i]     = __floats2half2_rn(v.x, v.y);
    ((__half2*)g_ahi)[2 * i + 1] = __floats2half2_rn(v.z, v.w);
}

template <int NO>
__global__ void k_split_wt(const float* __restrict__ W, __half* __restrict__ hi,
                           __half* __restrict__ lo) {
    int i = blockIdx.x * blockDim.x + threadIdx.x;
    if (i >= 256 * NO) return;
    int k = i / NO, n = i % NO;
    __half h, l;
    split2(W[i], h, l);
    hi[n * 256 + k] = h;
    lo[n * 256 + k] = l;
}

// ---------------- GEMM: 8 warps, A fp16, B hi/lo (2 passes), fused alpha ----------
template <int NO>
__global__ __launch_bounds__(256, 2) void k_gemm_mma(const __half* __restrict__ A,
                                                     const __half* __restrict__ Bhi,
                                                     const __half* __restrict__ Blo,
                                                     __half* __restrict__ Hhi,
                                                     const float* __restrict__ a_s,
                                                     const float* __restrict__ a_d) {
    constexpr int BM = 128, BN = (NO == 256) ? 128 : 64;
    constexpr int WN = BN / 2;
    constexpr int NG = WN / 8;
    constexpr int ASZ = 128 * 128;
    constexpr int BSZ = BN * 128;
    constexpr int STG = ASZ + 2 * BSZ;

    extern __shared__ __align__(1024) char smraw[];
    const uint32_t sb = smem_u32(smraw);
    const int tid = threadIdx.x, w = tid >> 5, lane = tid & 31;
    const int wm = w & 3, wn = w >> 2;
    const int bm = blockIdx.y * BM, bn = blockIdx.x * BN;

    auto load = [&](int c) {
        const uint32_t st = sb + (c & 1) * STG;
        const int ko = c * 64;
        for (int t = tid; t < 128 * 8; t += 256) {
            int r = t >> 3, q = t & 7;
            int gr = bm + r; if (gr >= NN) gr = NN - 1;
            cp_async16(st + SW128(r * 128 + q * 16), A + (size_t)gr * 256 + ko + q * 8);
        }
        for (int t = tid; t < BN * 8; t += 256) {
            int r = t >> 3, q = t & 7;
            size_t go = (size_t)(bn + r) * 256 + ko + q * 8;
            uint32_t so = SW128(r * 128 + q * 16);
            cp_async16(st + ASZ + so, Bhi + go);
            cp_async16(st + ASZ + BSZ + so, Blo + go);
        }
        asm volatile("cp.async.commit_group;" ::: "memory");
    };

    load(0);
    load(1);

    float acc[2][NG][4] = {};
    const int a_row = wm * 32 + (lane & 15);
    const int a_colq = (lane >> 4) * 16;
    const int b_row = wn * WN + (lane >> 4) * 8 + (lane & 7);
    const int b_colq = ((lane >> 3) & 1) * 16;

    for (int c = 0; c < 4; ++c) {
        const uint32_t st = sb + (c & 1) * STG;
        if (c < 3) asm volatile("cp.async.wait_group 1;" ::: "memory");
        else       asm volatile("cp.async.wait_group 0;" ::: "memory");
        __syncthreads();
#pragma unroll
        for (int kk = 0; kk < 4; ++kk) {
            uint32_t ah[8], bb[2 * NG];
#pragma unroll
            for (int f = 0; f < 2; ++f)
                ldsm_x4(ah[f * 4], ah[f * 4 + 1], ah[f * 4 + 2], ah[f * 4 + 3],
                        st + SW128((a_row + f * 16) * 128 + kk * 32 + a_colq));
#pragma unroll
            for (int g2 = 0; g2 < NG / 2; ++g2)
                ldsm_x4(bb[g2 * 4], bb[g2 * 4 + 1], bb[g2 * 4 + 2], bb[g2 * 4 + 3],
                        st + ASZ + SW128((b_row + g2 * 16) * 128 + kk * 32 + b_colq));
#pragma unroll
            for (int f = 0; f < 2; ++f)
#pragma unroll
                for (int g = 0; g < NG; ++g)
                    mma16816(acc[f][g], ah + f * 4, bb + g * 2);
#pragma unroll
            for (int g2 = 0; g2 < NG / 2; ++g2)
                ldsm_x4(bb[g2 * 4], bb[g2 * 4 + 1], bb[g2 * 4 + 2], bb[g2 * 4 + 3],
                        st + ASZ + BSZ + SW128((b_row + g2 * 16) * 128 + kk * 32 + b_colq));
#pragma unroll
            for (int f = 0; f < 2; ++f)
#pragma unroll
                for (int g = 0; g < NG; ++g)
                    mma16816(acc[f][g], ah + f * 4, bb + g * 2);
        }
        __syncthreads();
        if (c + 2 < 4) load(c + 2);
    }

    if constexpr (NO == 256) {
        const int head = blockIdx.x * 2 + wn;
        float as_r[2 * NG], ad_r[2 * NG];
#pragma unroll
        for (int g = 0; g < NG; ++g) {
            int cl = head * 64 + g * 8 + (lane & 3) * 2;
            as_r[g * 2] = a_s[cl];     as_r[g * 2 + 1] = a_s[cl + 1];
            ad_r[g * 2] = a_d[cl];     ad_r[g * 2 + 1] = a_d[cl + 1];
        }
#pragma unroll
        for (int f = 0; f < 2; ++f) {
#pragma unroll
            for (int rr = 0; rr < 2; ++rr) {
                float ps = 0.f, pd = 0.f;
#pragma unroll
                for (int g = 0; g < NG; ++g) {
                    float c0 = acc[f][g][rr * 2], c1 = acc[f][g][rr * 2 + 1];
                    ps += c0 * as_r[g * 2] + c1 * as_r[g * 2 + 1];
                    pd += c0 * ad_r[g * 2] + c1 * ad_r[g * 2 + 1];
                }
                ps += __shfl_xor_sync(0xffffffffu, ps, 1);
                ps += __shfl_xor_sync(0xffffffffu, ps, 2);
                pd += __shfl_xor_sync(0xffffffffu, pd, 1);
                pd += __shfl_xor_sync(0xffffffffu, pd, 2);
                int m = bm + wm * 32 + f * 16 + rr * 8 + (lane >> 2);
                if ((lane & 3) == 0 && m < NN) {
                    g_as[m * 4 + head] = ps;
                    g_ad[m * 4 + head] = pd;
                }
            }
        }
#pragma unroll
        for (int f = 0; f < 2; ++f) {
#pragma unroll
            for (int g = 0; g < NG; ++g) {
                int m = bm + wm * 32 + f * 16 + (lane >> 2);
                int n = bn + wn * 64 + g * 8 + (lane & 3) * 2;
#pragma unroll
                for (int rr = 0; rr < 2; ++rr) {
                    int mm = m + rr * 8;
                    if (mm < NN)
                        *(__half2*)(Hhi + (size_t)mm * NO + n) =
                            __floats2half2_rn(acc[f][g][rr * 2], acc[f][g][rr * 2 + 1]);
                }
            }
        }
    } else {
        // store Hhi
#pragma unroll
        for (int f = 0; f < 2; ++f) {
#pragma unroll
            for (int g = 0; g < NG; ++g) {
                int m = bm + wm * 32 + f * 16 + (lane >> 2);
                int n = bn + wn * WN + g * 8 + (lane & 3) * 2;
#pragma unroll
                for (int rr = 0; rr < 2; ++rr) {
                    int mm = m + rr * 8;
                    if (mm < NN)
                        *(__half2*)(Hhi + (size_t)mm * NO + n) =
                            __floats2half2_rn(acc[f][g][rr * 2], acc[f][g][rr * 2 + 1]);
                }
            }
        }
        // fused alpha (H=1): cross-warp (wn 0/1) reduction via reused tile smem
        float as_r[2 * NG], ad_r[2 * NG];
#pragma unroll
        for (int g = 0; g < NG; ++g) {
            int cl = wn * 32 + g * 8 + (lane & 3) * 2;
            as_r[g * 2] = a_s[cl];     as_r[g * 2 + 1] = a_s[cl + 1];
            ad_r[g * 2] = a_d[cl];     ad_r[g * 2 + 1] = a_d[cl + 1];
        }
        float psv[2][2], pdv[2][2];
#pragma unroll
        for (int f = 0; f < 2; ++f) {
#pragma unroll
            for (int rr = 0; rr < 2; ++rr) {
                float ps = 0.f, pd = 0.f;
#pragma unroll
                for (int g = 0; g < NG; ++g) {
                    float c0 = acc[f][g][rr * 2], c1 = acc[f][g][rr * 2 + 1];
                    ps += c0 * as_r[g * 2] + c1 * as_r[g * 2 + 1];
                    pd += c0 * ad_r[g * 2] + c1 * ad_r[g * 2 + 1];
                }
                ps += __shfl_xor_sync(0xffffffffu, ps, 1);
                ps += __shfl_xor_sync(0xffffffffu, ps, 2);
                pd += __shfl_xor_sync(0xffffffffu, pd, 1);
                pd += __shfl_xor_sync(0xffffffffu, pd, 2);
                psv[f][rr] = ps; pdv[f][rr] = pd;
            }
        }
        float* red = (float*)smraw;  // tiles dead after final sync; 256 floats
        if (wn == 0 && (lane & 3) == 0) {
#pragma unroll
            for (int f = 0; f < 2; ++f)
#pragma unroll
                for (int rr = 0; rr < 2; ++rr) {
                    int row = wm * 32 + f * 16 + rr * 8 + (lane >> 2);
                    red[row] = psv[f][rr];
                    red[128 + row] = pdv[f][rr];
                }
        }
        __syncthreads();
        if (wn == 1 && (lane & 3) == 0) {
#pragma unroll
            for (int f = 0; f < 2; ++f)
#pragma unroll
                for (int rr = 0; rr < 2; ++rr) {
                    int row = wm * 32 + f * 16 + rr * 8 + (lane >> 2);
                    int m = bm + row;
                    if (m < NN) {
                        g_as[m] = red[row] + psv[f][rr];
                        g_ad[m] = red[128 + row] + pdv[f][rr];
                    }
                }
        }
    }
}

// ---------------- CSR build -------------------------------------------------------
__global__ void k_zero_cnt() {
    int i = blockIdx.x * blockDim.x + threadIdx.x;
    if (i < NN) g_cnt[i] = 0;
}
__global__ void k_count(const int* __restrict__ ei) {
    int e = blockIdx.x * blockDim.x + threadIdx.x;
    if (e >= ET) return;
    int d = (e < EE) ? ei[EE + e] : (e - EE);
    atomicAdd(&g_cnt[d], 1);
}
__global__ void k_scan1() {
    __shared__ int sh[SCAN_B];
    int tid = threadIdx.x;
    int i = blockIdx.x * SCAN_B + tid;
    int v = (i < NN) ? g_cnt[i] : 0;
    sh[tid] = v;
    __syncthreads();
    for (int off = 1; off < SCAN_B; off <<= 1) {
        int t = (tid >= off) ? sh[tid - off] : 0;
        __syncthreads();
        sh[tid] += t;
        __syncthreads();
    }
    g_incl[i] = sh[tid];
    if (tid == SCAN_B - 1) g_bsum[blockIdx.x] = sh[tid];
}
__global__ void k_scan2() {
    if (threadIdx.x == 0) {
        int s = 0;
        for (int i = 0; i < NBLK; ++i) { int t = g_bsum[i]; g_bsum[i] = s; s += t; }
    }
}
__global__ void k_scan3() {
    int i = blockIdx.x * blockDim.x + threadIdx.x;
    if (i < NN) {
        int v = g_cnt[i];
        int ex = g_incl[i] - v + g_bsum[i >> 10];
        g_rowptr[i] = ex;
        g_fill[i] = ex;
    }
    if (i == 0) g_rowptr[NN] = ET;
}
__global__ void k_fill(const int* __restrict__ ei) {
    int e = blockIdx.x * blockDim.x + threadIdx.x;
    if (e >= ET) return;
    int s, d;
    if (e < EE) { s = ei[e]; d = ei[EE + e]; }
    else        { s = e - EE; d = s; }
    int pos = atomicAdd(&g_fill[d], 1);
    g_col[pos] = s;
}

// ---------------- GAT conv: online softmax + fp16 message gather ------------------
template <int HEADS, bool RELU, bool SPLIT>
__global__ __launch_bounds__(256) void k_conv(const float* __restrict__ as_,
                                              const float* __restrict__ ad_,
                                              const float* __restrict__ bias,
                                              float* __restrict__ out,
                                              __half* __restrict__ ohi) {
    const int TC = HEADS * 64;
    const int NPL = TC / 32;
    int warp = (blockIdx.x * blockDim.x + threadIdx.x) >> 5;
    int lane = threadIdx.x & 31;
    if (warp >= NN) return;
    int beg = g_rowptr[warp], end = g_rowptr[warp + 1];

    float adh[HEADS];
#pragma unroll
    for (int hh = 0; hh < HEADS; ++hh) adh[hh] = ad_[warp * HEADS + hh];

    float mx[HEADS], sm[HEADS];
#pragma unroll
    for (int hh = 0; hh < HEADS; ++hh) { mx[hh] = -1e30f; sm[hh] = 0.f; }
    for (int i = beg + lane; i < end; i += 32) {
        int s = g_col[i];
        float ev[HEADS];
        if constexpr (HEADS == 4) {
            float4 a4 = ((const float4*)as_)[s];
            ev[0] = a4.x; ev[1] = a4.y; ev[2] = a4.z; ev[3] = a4.w;
        } else {
            ev[0] = as_[s];
        }
#pragma unroll
        for (int hh = 0; hh < HEADS; ++hh) {
            float e = ev[hh] + adh[hh];
            e = e > 0.f ? e : 0.2f * e;
            if (e > mx[hh]) {
                sm[hh] = sm[hh] * __expf(mx[hh] - e) + 1.f;
                mx[hh] = e;
            } else {
                sm[hh] += __expf(e - mx[hh]);
            }
        }
    }
#pragma unroll
    for (int hh = 0; hh < HEADS; ++hh) {
#pragma unroll
        for (int o = 16; o; o >>= 1) {
            float mo = __shfl_xor_sync(0xffffffffu, mx[hh], o);
            float so = __shfl_xor_sync(0xffffffffu, sm[hh], o);
            float mn = fmaxf(mx[hh], mo);
            sm[hh] = sm[hh] * __expf(mx[hh] - mn) + so * __expf(mo - mn);
            mx[hh] = mn;
        }
    }

    const int myhead = (lane * NPL) / 64;
    float mm = mx[myhead], adm = adh[myhead], inv = 1.f / sm[myhead];
    float acc[NPL] = {};
#pragma unroll 4
    for (int i = beg; i < end; ++i) {
        int s = g_col[i];
        float e = as_[s * HEADS + myhead] + adm;
        e = e > 0.f ? e : 0.2f * e;
        float w = __expf(e - mm) * inv;
        const __half* hp = g_hhi + (size_t)s * TC + lane * NPL;
        if constexpr (NPL == 8) {
            uint4 raw = *(const uint4*)hp;
            float2 f0 = __half22float2(*(__half2*)&raw.x);
            float2 f1 = __half22float2(*(__half2*)&raw.y);
            float2 f2 = __half22float2(*(__half2*)&raw.z);
            float2 f3 = __half22float2(*(__half2*)&raw.w);
            acc[0] += w * f0.x; acc[1] += w * f0.y; acc[2] += w * f1.x; acc[3] += w * f1.y;
            acc[4] += w * f2.x; acc[5] += w * f2.y; acc[6] += w * f3.x; acc[7] += w * f3.y;
        } else {
            uint32_t raw = *(const uint32_t*)hp;
            float2 f0 = __half22float2(*(__half2*)&raw);
            acc[0] += w * f0.x; acc[1] += w * f0.y;
        }
    }
    float dinv = 1.f / (float)(end - beg);
    float v[NPL];
#pragma unroll
    for (int j = 0; j < NPL; ++j) {
        v[j] = acc[j] * dinv + bias[lane * NPL + j];
        if (RELU) v[j] = fmaxf(v[j], 0.f);
    }
    if constexpr (SPLIT) {
        __half2 vh[NPL / 2];
#pragma unroll
        for (int j = 0; j < NPL / 2; ++j)
            vh[j] = __floats2half2_rn(v[2 * j], v[2 * j + 1]);
        *(uint4*)(ohi + (size_t)warp * TC + lane * NPL) = *(uint4*)vh;
    } else {
#pragma unroll
        for (int j = 0; j < NPL; ++j)
            out[(size_t)warp * TC + lane * NPL + j] = v[j];
    }
}

// ---------------- launch ----------------------------------------------------------
extern "C" void kernel_launch(void* const* d_in, const int* in_sizes, int n_in,
                              void* d_out, int out_size) {
    const float* x   = (const float*)d_in[0];
    const int*   ei  = (const int*)d_in[1];
    const float* W0  = (const float*)d_in[2];
    const float* a0s = (const float*)d_in[3];
    const float* a0d = (const float*)d_in[4];
    const float* b0  = (const float*)d_in[5];
    const float* W1  = (const float*)d_in[6];
    const float* a1s = (const float*)d_in[7];
    const float* a1d = (const float*)d_in[8];
    const float* b1  = (const float*)d_in[9];
    const float* W2  = (const float*)d_in[10];
    const float* a2s = (const float*)d_in[11];
    const float* a2d = (const float*)d_in[12];
    const float* b2  = (const float*)d_in[13];
    float* out = (float*)d_out;

    void* p;
    cudaGetSymbolAddress(&p, g_ahi);  __half* ahi = (__half*)p;
    cudaGetSymbolAddress(&p, g_hhi);  __half* hhi = (__half*)p;
    cudaGetSymbolAddress(&p, g_w0hi); __half* w0hi = (__half*)p;
    cudaGetSymbolAddress(&p, g_w0lo); __half* w0lo = (__half*)p;
    cudaGetSymbolAddress(&p, g_w1hi); __half* w1hi = (__half*)p;
    cudaGetSymbolAddress(&p, g_w1lo); __half* w1lo = (__half*)p;
    cudaGetSymbolAddress(&p, g_w2hi); __half* w2hi = (__half*)p;
    cudaGetSymbolAddress(&p, g_w2lo); __half* w2lo = (__half*)p;
    cudaGetSymbolAddress(&p, g_as);   float* asb = (float*)p;
    cudaGetSymbolAddress(&p, g_ad);   float* adb = (float*)p;

    const int SMEM256 = 2 * (128 * 128 + 2 * 128 * 128);  // 98304
    const int SMEM64  = 2 * (128 * 128 + 2 * 64 * 128);   // 65536

    static cudaStream_t s2 = nullptr;
    static cudaEvent_t ev_fork, ev_w0, ev_join;
    if (!s2) {
        cudaFuncSetAttribute(k_gemm_mma<256>, cudaFuncAttributeMaxDynamicSharedMemorySize, SMEM256);
        cudaFuncSetAttribute(k_gemm_mma<64>,  cudaFuncAttributeMaxDynamicSharedMemorySize, SMEM64);
        cudaStreamCreateWithFlags(&s2, cudaStreamNonBlocking);
        cudaEventCreateWithFlags(&ev_fork, cudaEventDisableTiming);
        cudaEventCreateWithFlags(&ev_w0,   cudaEventDisableTiming);
        cudaEventCreateWithFlags(&ev_join, cudaEventDisableTiming);
    }

    const int WPB = 8;
    const int NODE_BLKS = (NN + WPB - 1) / WPB;
    dim3 g256(2, (NN + 127) / 128);
    dim3 g64(1, (NN + 127) / 128);

    // fork: side stream does W0 split first, then CSR build + W1/W2 splits
    cudaEventRecord(ev_fork, 0);
    cudaStreamWaitEvent(s2, ev_fork, 0);
    k_split_wt<256><<<(256 * 256 + 255) / 256, 256, 0, s2>>>(W0, w0hi, w0lo);
    cudaEventRecord(ev_w0, s2);
    k_zero_cnt<<<(NN + 255) / 256, 256, 0, s2>>>();
    k_count<<<(ET + 255) / 256, 256, 0, s2>>>(ei);
    k_scan1<<<NBLK, SCAN_B, 0, s2>>>();
    k_scan2<<<1, 32, 0, s2>>>();
    k_scan3<<<(NN + 255) / 256, 256, 0, s2>>>();
    k_fill<<<(ET + 255) / 256, 256, 0, s2>>>(ei);
    k_split_wt<256><<<(256 * 256 + 255) / 256, 256, 0, s2>>>(W1, w1hi, w1lo);
    k_split_wt<64><<<(256 * 64 + 255) / 256, 256, 0, s2>>>(W2, w2hi, w2lo);
    cudaEventRecord(ev_join, s2);

    // main stream: layer-0 GEMM chain
    k_tofp16_x<<<(NN * 64 + 255) / 256, 256>>>(x);
    cudaStreamWaitEvent(0, ev_w0, 0);
    k_gemm_mma<256><<<g256, 256, SMEM256>>>(ahi, w0hi, w0lo, hhi, a0s, a0d);

    // join: conv0 needs CSR (+ W1/W2 ready for later)
    cudaStreamWaitEvent(0, ev_join, 0);
    k_conv<4, true, true><<<NODE_BLKS, 256>>>(asb, adb, b0, nullptr, ahi);

    // layer 1
    k_gemm_mma<256><<<g256, 256, SMEM256>>>(ahi, w1hi, w1lo, hhi, a1s, a1d);
    k_conv<4, true, true><<<NODE_BLKS, 256>>>(asb, adb, b1, nullptr, ahi);

    // layer 2 (heads=1, alpha fused in GEMM epilogue)
    k_gemm_mma<64><<<g64, 256, SMEM64>>>(ahi, w2hi, w2lo, hhi, a2s, a2d);
    k_conv<1, false, false><<<NODE_BLKS, 256>>>(asb, adb, b2, out, nullptr);
}